// round 3
// baseline (speedup 1.0000x reference)
#include <cuda_runtime.h>
#include <math.h>

#define BATCH 64
#define N 256
#define NT 256
#define INF_F 1e30f
#define ARR_CAP 1024

// per-batch matched-distance sums (deterministic, no atomics)
__device__ float g_batch_sum[BATCH];

// order-preserving float <-> uint map (min on uint == min on float, non-NaN)
__device__ __forceinline__ unsigned fmap(float f) {
    unsigned b = __float_as_uint(f);
    return (b & 0x80000000u) ? ~b : (b | 0x80000000u);
}
__device__ __forceinline__ float funmap(unsigned m) {
    return __uint_as_float((m & 0x80000000u) ? (m & 0x7fffffffu) : ~m);
}

__global__ void __launch_bounds__(NT, 1)
hungarian_kernel(const float* __restrict__ pred,
                 const float* __restrict__ target)
{
    const int b = blockIdx.x;
    const int t = threadIdx.x;      // thread t owns column j = t+1 (1-based)
    const int j = t + 1;

    __shared__ float spx[N], spy[N], spz[N];     // pred points (rows)
    __shared__ float su[N + 1];                  // row potentials u[1..N]
    __shared__ short sp[N + 1];                  // p[j] = row matched to col j (1-based; 0=free)
    __shared__ short sway[N + 1];                // predecessor column on path
    __shared__ short sargr[N];                   // argmin row per column (0-based)
    __shared__ unsigned char srowm[N];           // row matched flag (prematch)
    __shared__ short squeue[256];                // ring buffer of unassigned rows (1-based)
    __shared__ short sunm[N];                    // rows left for exact path phase
    __shared__ int   s_cur;                      // ARR: current row (0 = done)
    __shared__ int   s_nunm;
    __shared__ unsigned long long rbuf[2][8];    // double-buffered warp (min|idx)
    __shared__ unsigned rbuf2[2][8];             // warp second-min
    __shared__ float fsum[8];

    // ---- load points ----
    const float* pb = pred   + (size_t)b * N * 3;
    const float* tb = target + (size_t)b * N * 3;
    spx[t] = pb[t * 3 + 0];
    spy[t] = pb[t * 3 + 1];
    spz[t] = pb[t * 3 + 2];
    const float tx = tb[t * 3 + 0];
    const float ty = tb[t * 3 + 1];
    const float tz = tb[t * 3 + 2];

    su[t] = 0.0f;
    sp[t] = 0;
    srowm[t] = 0;
    if (t == 0) { su[N] = 0.0f; sp[N] = 0; }
    __syncthreads();

    // ---- JV column reduction: v[j] = min_i c(i,j), remember argmin row ----
    float v = INF_F;
    int rmin = 0;
    #pragma unroll 4
    for (int i = 0; i < N; ++i) {
        const float dx = spx[i] - tx;
        const float dy = spy[i] - ty;
        const float dz = spz[i] - tz;
        const float d = sqrtf(fmaf(dx, dx, fmaf(dy, dy, dz * dz)));
        if (d < v) { v = d; rmin = i; }
    }
    sargr[t] = (short)rmin;
    __syncthreads();

    // ---- greedy pre-match on tight edges + build free-row queue (t0) ----
    int qhead = 0, qtail = 0;   // meaningful on t0 only
    if (t == 0) {
        for (int jj = 1; jj <= N; ++jj) {
            const int r = sargr[jj - 1];
            if (!srowm[r]) { srowm[r] = 1; sp[jj] = (short)(r + 1); }
        }
        for (int i = 0; i < N; ++i)
            if (!srowm[i]) squeue[(qtail++) & 255] = (short)(i + 1);
        s_cur = (qtail > qhead) ? (int)squeue[(qhead++) & 255] : 0;
    }
    __syncthreads();

    // ================= Augmenting Row Reduction (JV) =================
    // For the current free row i: u1 = min_j (c[i][j]-v[j]) at j1,
    // u2 = second min. Set u[i]=u2; if u1<u2 lower v[j1]; take j1,
    // displaced row continues the chain (or is re-queued on ties).
    // Every assignment stays tight vs feasible duals => exact.
    int iters = 0;
    for (;;) {
        const int i = s_cur;
        if (i == 0) break;

        const float px = spx[i - 1];      // broadcast LDS
        const float py = spy[i - 1];
        const float pz = spz[i - 1];
        const float dx = px - tx;
        const float dy = py - ty;
        const float dz = pz - tz;
        const float cur = sqrtf(fmaf(dx, dx, fmaf(dy, dy, dz * dz))) - v;

        // warp min + second-min (dup-safe: masking one min lane leaves dup)
        const unsigned key  = fmap(cur);
        const unsigned wmin = __reduce_min_sync(0xffffffffu, key);
        const unsigned ball = __ballot_sync(0xffffffffu, key == wmin);
        const int lane1 = __ffs(ball) - 1;
        const int widx  = __shfl_sync(0xffffffffu, j, lane1);
        const unsigned keym = ((t & 31) == lane1) ? 0xffffffffu : key;
        const unsigned wmin2 = __reduce_min_sync(0xffffffffu, keym);

        const int par = iters & 1;
        if ((t & 31) == 0) {
            rbuf[par][t >> 5]  = ((unsigned long long)wmin << 32) | (unsigned)widx;
            rbuf2[par][t >> 5] = wmin2;
        }
        __syncthreads();

        // block min2 combine (redundant on all threads)
        unsigned best1 = 0xffffffffu, best2 = 0xffffffffu;
        int bidx = 1;
        #pragma unroll
        for (int w = 0; w < 8; ++w) {
            const unsigned long long e = rbuf[par][w];
            const unsigned e1 = (unsigned)(e >> 32);
            const unsigned e2 = rbuf2[par][w];
            if (e1 < best1) {
                best2 = best1 < e2 ? best1 : e2;
                best1 = e1;
                bidx  = (int)(e & 0xffffffffu);
            } else {
                best2 = best2 < e1 ? best2 : e1;
            }
        }
        const unsigned u1k = best1, u2k = best2;
        const int j1 = bidx;

        if (j == j1 && u1k < u2k)
            v -= (funmap(u2k) - funmap(u1k));

        if (t == 0) {
            const int k = sp[j1];
            sp[j1] = (short)i;
            su[i]  = funmap(u2k);
            int nxt = 0;
            if (k > 0 && u1k < u2k && iters + 1 < ARR_CAP) {
                nxt = k;                       // continue steal chain
            } else {
                if (k > 0) squeue[(qtail++) & 255] = (short)k;   // tie/cap: requeue
                if (qtail > qhead && iters + 1 < ARR_CAP)
                    nxt = (int)squeue[(qhead++) & 255];
            }
            s_cur = nxt;
        }
        ++iters;
        __syncthreads();
    }

    // remaining free rows -> exact path phase
    if (t == 0) {
        const int cnt = qtail - qhead;
        for (int ii = 0; ii < cnt; ++ii)
            sunm[ii] = squeue[(qhead + ii) & 255];
        s_nunm = cnt;
    }
    __syncthreads();
    const int nunm = s_nunm;

    // ====== exact augmenting paths (Dijkstra, deferred dual updates) ======
    for (int ii = 0; ii < nunm; ++ii) {
        const int i = sunm[ii];
        float shortestj = INF_F;   // absolute shortest-path cost to column j
        bool  used = false;
        int   myrow = 0;
        if (t == 0) sp[0] = (short)i;
        __syncthreads();

        int   j0 = 0;
        float minVal = 0.0f;
        int   step = 0;
        for (;;) {
            const int i0 = sp[j0];
            if (j == j0) { used = true; myrow = i0; }

            if (!used) {
                const float ddx = spx[i0 - 1] - tx;
                const float ddy = spy[i0 - 1] - ty;
                const float ddz = spz[i0 - 1] - tz;
                const float cu = minVal - su[i0] - v +
                                 sqrtf(fmaf(ddx, ddx, fmaf(ddy, ddy, ddz * ddz)));
                if (cu < shortestj) { shortestj = cu; sway[j] = (short)j0; }
            }

            const unsigned key  = fmap(used ? INF_F : shortestj);
            const unsigned wmin = __reduce_min_sync(0xffffffffu, key);
            const unsigned ball = __ballot_sync(0xffffffffu, key == wmin);
            const int lane = __ffs(ball) - 1;
            const int widx = __shfl_sync(0xffffffffu, j, lane);
            const int buf = step & 1;
            if ((t & 31) == 0)
                rbuf[buf][t >> 5] = ((unsigned long long)wmin << 32) | (unsigned)widx;
            __syncthreads();

            unsigned long long best = rbuf[buf][0];
            #pragma unroll
            for (int w = 1; w < 8; ++w) {
                const unsigned long long x = rbuf[buf][w];
                if (x < best) best = x;
            }
            minVal = funmap((unsigned)(best >> 32));
            const int j1 = (int)(best & 0xffffffffu);

            if (sp[j1] == 0) {
                __syncthreads();       // everyone has read sp[j1]
                if (used) {
                    const float d = minVal - shortestj;
                    v -= d;
                    su[myrow] += d;
                }
                if (t == 0) {
                    su[i] += minVal;
                    int jj = j1;
                    while (jj) {
                        const int jn = sway[jj];
                        sp[jj] = sp[jn];
                        jj = jn;
                    }
                }
                __syncthreads();
                break;
            }
            j0 = j1;
            ++step;
        }
    }

    // ---- matched distance for my column: row sp[j]-1 <-> target[j-1] ----
    const int r = sp[j] - 1;
    const float dx = spx[r] - tx;
    const float dy = spy[r] - ty;
    const float dz = spz[r] - tz;
    float md = sqrtf(fmaf(dx, dx, fmaf(dy, dy, dz * dz)));

    #pragma unroll
    for (int o = 16; o > 0; o >>= 1)
        md += __shfl_down_sync(0xffffffffu, md, o);
    if ((t & 31) == 0) fsum[t >> 5] = md;
    __syncthreads();
    if (t == 0) {
        float s = 0.0f;
        #pragma unroll
        for (int w = 0; w < 8; ++w) s += fsum[w];
        g_batch_sum[b] = s;
    }
}

__global__ void finalize_kernel(float* __restrict__ out)
{
    double s = 0.0;
    #pragma unroll
    for (int b = 0; b < BATCH; ++b) s += (double)g_batch_sum[b];
    out[0] = (float)(s / (double)BATCH);
}

extern "C" void kernel_launch(void* const* d_in, const int* in_sizes, int n_in,
                              void* d_out, int out_size)
{
    const float* pred   = (const float*)d_in[0];
    const float* target = (const float*)d_in[1];
    float* out = (float*)d_out;

    hungarian_kernel<<<BATCH, NT>>>(pred, target);
    finalize_kernel<<<1, 1>>>(out);
}

// round 5
// speedup vs baseline: 1.1828x; 1.1828x over previous
#include <cuda_runtime.h>
#include <math.h>

#define BATCH 64
#define N 256
#define NT 128
#define KC 2
#define INF_F 1e30f

// per-batch matched-distance sums (deterministic, no atomics)
__device__ float g_batch_sum[BATCH];

// order-preserving float <-> uint map (min on uint == min on float, non-NaN)
__device__ __forceinline__ unsigned fmap(float f) {
    unsigned b = __float_as_uint(f);
    return (b & 0x80000000u) ? ~b : (b | 0x80000000u);
}
__device__ __forceinline__ float funmap(unsigned m) {
    return __uint_as_float((m & 0x80000000u) ? (m & 0x7fffffffu) : ~m);
}
__device__ __forceinline__ float sqrt_approx(float x) {
    float r;
    asm("sqrt.approx.f32 %0, %1;" : "=f"(r) : "f"(x));
    return r;
}

__global__ void __launch_bounds__(NT, 1)
hungarian_kernel(const float* __restrict__ pred,
                 const float* __restrict__ target)
{
    const int b = blockIdx.x;
    const int t = threadIdx.x;      // thread t owns columns t+1 and t+129 (1-based)

    __shared__ float4 spt[N];                    // pred xyz; .w = row potential u
    __shared__ short  sp[N + 1];                 // p[j] = row matched to col j (1-based; 0=free)
    __shared__ short  sway[N + 1];               // predecessor column on path
    __shared__ short  sargr[N];                  // argmin row per column (0-based)
    __shared__ unsigned char srowm[N];           // row matched flag (prematch)
    __shared__ short  sunm[N];                   // free rows for path phase
    __shared__ int    s_nunm;
    __shared__ unsigned long long rbuf[2][4];    // double-buffered warp (min|idx)
    __shared__ float  fsum[4];

    // ---- load points ----
    const float* pb = pred   + (size_t)b * N * 3;
    const float* tb = target + (size_t)b * N * 3;
    #pragma unroll
    for (int k = 0; k < KC; ++k) {
        const int r = t + k * NT;
        spt[r] = make_float4(pb[r * 3], pb[r * 3 + 1], pb[r * 3 + 2], 0.0f);
        sp[r] = 0;
        srowm[r] = 0;
    }
    float tx[KC], ty[KC], tz[KC];
    #pragma unroll
    for (int k = 0; k < KC; ++k) {
        const int c = t + k * NT;
        tx[k] = tb[c * 3 + 0];
        ty[k] = tb[c * 3 + 1];
        tz[k] = tb[c * 3 + 2];
    }
    if (t == 0) sp[N] = 0;
    __syncthreads();

    // ---- column reduction on SQUARED distance (sqrt monotonic) ----
    float v[KC];
    {
        float bd2[KC] = {INF_F, INF_F};
        int   br[KC]  = {0, 0};
        #pragma unroll 2
        for (int r = 0; r < N; ++r) {
            const float4 p = spt[r];
            #pragma unroll
            for (int k = 0; k < KC; ++k) {
                const float dx = p.x - tx[k];
                const float dy = p.y - ty[k];
                const float dz = p.z - tz[k];
                const float d2 = fmaf(dx, dx, fmaf(dy, dy, dz * dz));
                if (d2 < bd2[k]) { bd2[k] = d2; br[k] = r; }
            }
        }
        #pragma unroll
        for (int k = 0; k < KC; ++k) {
            v[k] = sqrt_approx(bd2[k]);
            sargr[t + k * NT] = (short)br[k];
        }
    }
    __syncthreads();

    // ---- greedy pre-match on tight edges + free-row list (t0, serial) ----
    if (t == 0) {
        for (int jj = 1; jj <= N; ++jj) {
            const int r = sargr[jj - 1];
            if (!srowm[r]) { srowm[r] = 1; sp[jj] = (short)(r + 1); }
        }
        int cnt = 0;
        for (int r = 0; r < N; ++r)
            if (!srowm[r]) sunm[cnt++] = (short)(r + 1);
        s_nunm = cnt;
    }
    __syncthreads();
    const int nunm = s_nunm;

    // ====== exact augmenting paths (Dijkstra, deferred dual updates) ======
    for (int ii = 0; ii < nunm; ++ii) {
        const int istart = sunm[ii];
        float shortest[KC] = {INF_F, INF_F};
        int   myrow[KC]    = {0, 0};
        unsigned usedm = 0;
        float minVal = 0.0f;
        int   i0 = istart;          // row on column j0 (carried; = sp[j0])
        int   j0 = 0;
        int   step = 0;
        for (;;) {
            // mark my column used if it is j0 (record its matched row now)
            if (j0 && ((j0 - 1) & 127) == t) {
                const int k = (j0 - 1) >> 7;
                usedm |= 1u << k;
                myrow[k] = i0;
            }

            const float4 p = spt[i0 - 1];       // xyz + u[i0], one LDS.128 bcast
            const float base = minVal - p.w;
            #pragma unroll
            for (int k = 0; k < KC; ++k) {
                if (!((usedm >> k) & 1u)) {
                    const float dx = p.x - tx[k];
                    const float dy = p.y - ty[k];
                    const float dz = p.z - tz[k];
                    const float cur = base - v[k] +
                        sqrt_approx(fmaf(dx, dx, fmaf(dy, dy, dz * dz)));
                    if (cur < shortest[k]) {
                        shortest[k] = cur;
                        sway[t + k * NT + 1] = (short)j0;
                    }
                }
            }

            // local argmin over my 2 columns
            const float lv0 = (usedm & 1u)        ? INF_F : shortest[0];
            const float lv1 = ((usedm >> 1) & 1u) ? INF_F : shortest[1];
            float lval; int lidx;
            if (lv1 < lv0) { lval = lv1; lidx = t + NT + 1; }
            else           { lval = lv0; lidx = t + 1; }

            // warp + block argmin (1 barrier)
            const unsigned key  = fmap(lval);
            const unsigned wmin = __reduce_min_sync(0xffffffffu, key);
            const unsigned ball = __ballot_sync(0xffffffffu, key == wmin);
            const int lane = __ffs(ball) - 1;
            const int widx = __shfl_sync(0xffffffffu, lidx, lane);
            const int buf = step & 1;
            if ((t & 31) == 0)
                rbuf[buf][t >> 5] = ((unsigned long long)wmin << 32) | (unsigned)widx;
            __syncthreads();

            unsigned long long best = rbuf[buf][0];
            #pragma unroll
            for (int w = 1; w < 4; ++w) {
                const unsigned long long x = rbuf[buf][w];
                if (x < best) best = x;
            }
            minVal = funmap((unsigned)(best >> 32));
            const int j1  = (int)(best & 0xffffffffu);
            const int i0n = sp[j1];             // doubles as next step's sp[j0]

            if (i0n == 0) {
                __syncthreads();                // all reads of sp/sway done
                #pragma unroll
                for (int k = 0; k < KC; ++k) {
                    if ((usedm >> k) & 1u) {
                        const float d = minVal - shortest[k];
                        v[k] -= d;
                        spt[myrow[k] - 1].w += d;   // distinct rows: no conflict
                    }
                }
                if (t == 0) {
                    spt[istart - 1].w += minVal;
                    sp[0] = (short)istart;      // path terminus picks up the free row
                    int jj = j1;
                    while (jj) {
                        const int jn = sway[jj];
                        sp[jj] = sp[jn];
                        jj = jn;
                    }
                }
                __syncthreads();
                break;
            }
            j0 = j1;
            i0 = i0n;
            ++step;
        }
    }

    // ---- matched distances (exact sqrt) ----
    float md = 0.0f;
    #pragma unroll
    for (int k = 0; k < KC; ++k) {
        const int r = sp[t + k * NT + 1] - 1;
        const float4 p = spt[r];
        const float dx = p.x - tx[k];
        const float dy = p.y - ty[k];
        const float dz = p.z - tz[k];
        md += sqrtf(fmaf(dx, dx, fmaf(dy, dy, dz * dz)));
    }
    #pragma unroll
    for (int o = 16; o > 0; o >>= 1)
        md += __shfl_down_sync(0xffffffffu, md, o);
    if ((t & 31) == 0) fsum[t >> 5] = md;
    __syncthreads();
    if (t == 0) {
        float s = 0.0f;
        #pragma unroll
        for (int w = 0; w < 4; ++w) s += fsum[w];
        g_batch_sum[b] = s;
    }
}

__global__ void finalize_kernel(float* __restrict__ out)
{
    double s = 0.0;
    #pragma unroll
    for (int b = 0; b < BATCH; ++b) s += (double)g_batch_sum[b];
    out[0] = (float)(s / (double)BATCH);
}

extern "C" void kernel_launch(void* const* d_in, const int* in_sizes, int n_in,
                              void* d_out, int out_size)
{
    const float* pred   = (const float*)d_in[0];
    const float* target = (const float*)d_in[1];
    float* out = (float*)d_out;

    hungarian_kernel<<<BATCH, NT>>>(pred, target);
    finalize_kernel<<<1, 1>>>(out);
}